// round 11
// baseline (speedup 1.0000x reference)
#include <cuda_runtime.h>
#include <math.h>

#define NNODE 512
#define NWIN  64
#define NE    26000
#define NCTA  128
#define MAXD  224
#define NGRP  8          // barrier tree: 8 groups x 16 CTAs

// ---------------- device scratch ----------------
__device__ float g_X  [NWIN*NNODE*32];
__device__ float g_XF1[NWIN*NNODE*32];
__device__ float g_XB1[NWIN*NNODE*32];
__device__ float g_XT2O[NWIN*NNODE*32];   // 2*Pf(XF1) - X  (finished Chebyshev-2 x-term, fwd)
__device__ float g_XT2I[NWIN*NNODE*32];   // 2*Pb(XB1) - X
__device__ float g_H  [NNODE*32];
__device__ float g_V  [NNODE*32];
__device__ float g_HF1[NNODE*32];
__device__ float g_HB1[NNODE*32];
__device__ float g_VF1[NNODE*32];
__device__ float g_VB1[NNODE*32];
__device__ float g_Wcat[3*320*32];
__device__ float g_bias[96];
__device__ int   g_deg_out[NNODE], g_deg_in[NNODE];
__device__ float g_dinv_out[NNODE], g_dinv_in[NNODE];
__device__ int   g_base_dst[NNODE+1], g_base_src[NNODE+1];
__device__ int   g_adj_dst_n[NE];
__device__ float g_adj_dst_w[NE];
__device__ int   g_adj_src_n[NE];
__device__ float g_adj_src_w[NE];
__device__ unsigned g_grp[NGRP*32];          // group counters, 128B apart
__device__ unsigned g_root;
__device__ volatile unsigned g_gen;
__device__ float g_lin1out[8192];
__device__ float g_c1out[2048];

// ---------------- f32x2 packed math helpers ----------------
__device__ __forceinline__ unsigned long long pk2(float lo, float hi) {
    unsigned long long r;
    asm("mov.b64 %0, {%1, %2};" : "=l"(r) : "f"(lo), "f"(hi));
    return r;
}
__device__ __forceinline__ void fma2(unsigned long long& d, unsigned long long a, unsigned long long b) {
    asm("fma.rn.f32x2 %0, %1, %2, %0;" : "+l"(d) : "l"(a), "l"(b));
}
__device__ __forceinline__ float2 upk2(unsigned long long v) {
    float2 r;
    asm("mov.b64 {%0, %1}, %2;" : "=f"(r.x), "=f"(r.y) : "l"(v));
    return r;
}

// ---------------- prep kernels ----------------
__global__ void k0() {
    int i = blockIdx.x * blockDim.x + threadIdx.x;
    if (i < NNODE*32) g_H[i] = 0.f;
    if (i < NNODE) { g_deg_in[i] = 0; g_deg_out[i] = 0; }
    if (i < NGRP*32) g_grp[i] = 0u;
    if (i == 0) { g_root = 0u; g_gen = 0u; }
}

__global__ void k_deg(const int* __restrict__ ei) {
    int e = blockIdx.x * blockDim.x + threadIdx.x;
    if (e < NE) {
        atomicAdd(&g_deg_out[ei[e]], 1);
        atomicAdd(&g_deg_in [ei[NE + e]], 1);
    }
}

__global__ void k_scan() {   // 1 block, 512 threads
    __shared__ int s[NNODE];
    int t = threadIdx.x;
    int dgi = g_deg_in[t], dgo = g_deg_out[t];
    g_dinv_in [t] = dgi > 0 ? 1.f / (float)dgi : 0.f;
    g_dinv_out[t] = dgo > 0 ? 1.f / (float)dgo : 0.f;
    s[t] = dgi; __syncthreads();
    for (int off = 1; off < NNODE; off <<= 1) {
        int v = (t >= off) ? s[t - off] : 0;
        __syncthreads(); s[t] += v; __syncthreads();
    }
    g_base_dst[t + 1] = s[t];
    if (t == 0) g_base_dst[0] = 0;
    __syncthreads();
    s[t] = dgo; __syncthreads();
    for (int off = 1; off < NNODE; off <<= 1) {
        int v = (t >= off) ? s[t - off] : 0;
        __syncthreads(); s[t] += v; __syncthreads();
    }
    g_base_src[t + 1] = s[t];
    if (t == 0) g_base_src[0] = 0;
}

// deterministic CSR: one warp per (node, direction), warp-ballot ordered by edge id
__global__ void k_csr(const int* __restrict__ ei) {
    int gw = (blockIdx.x * blockDim.x + threadIdx.x) >> 5;
    int lane = threadIdx.x & 31;
    const int* src = ei;
    const int* dst = ei + NE;
    if (gw < NNODE) {
        int n = gw, base = g_base_dst[n], cnt = 0;
        for (int e0 = 0; e0 < NE; e0 += 32) {
            int e = e0 + lane;
            bool m = (e < NE) && (dst[e] == n);
            unsigned mask = __ballot_sync(0xffffffffu, m);
            if (m) {
                int pos = cnt + __popc(mask & ((1u << lane) - 1u));
                int sv = src[e];
                g_adj_dst_n[base + pos] = sv;
                g_adj_dst_w[base + pos] = g_dinv_out[sv];
            }
            cnt += __popc(mask);
        }
    } else if (gw < 2 * NNODE) {
        int n = gw - NNODE, base = g_base_src[n], cnt = 0;
        for (int e0 = 0; e0 < NE; e0 += 32) {
            int e = e0 + lane;
            bool m = (e < NE) && (src[e] == n);
            unsigned mask = __ballot_sync(0xffffffffu, m);
            if (m) {
                int pos = cnt + __popc(mask & ((1u << lane) - 1u));
                int dv = dst[e];
                g_adj_src_n[base + pos] = dv;
                g_adj_src_w[base + pos] = g_dinv_in[dv];
            }
            cnt += __popc(mask);
        }
    }
}

// Wcat layout: [gate][j][o], j = blk*64 + c with blocks {xh, t1o, t1i, t2o, t2i}
__global__ void k_wcat(const float* __restrict__ wz, const float* __restrict__ wr,
                       const float* __restrict__ wh, const float* __restrict__ bz,
                       const float* __restrict__ br, const float* __restrict__ bh) {
    int idx = blockIdx.x * blockDim.x + threadIdx.x;
    if (idx < 96) g_bias[idx] = (idx < 32) ? bz[idx] : (idx < 64) ? br[idx-32] : bh[idx-64];
    if (idx >= 3*320*32) return;
    int g = idx / 10240, rem = idx % 10240;
    int j = rem >> 5, o = rem & 31;
    const float* W = (g == 0) ? wz : (g == 1) ? wr : wh;   // [2][3][64][32]
    int c = j & 63, blk = j >> 6;
    float v;
    if      (blk == 0) v = W[c*32 + o] + W[(192 + c)*32 + o];   // W[0,0]+W[1,0]
    else if (blk == 1) v = W[( 64 + c)*32 + o];                 // W[0,1]
    else if (blk == 2) v = W[(256 + c)*32 + o];                 // W[1,1]
    else if (blk == 3) v = W[(128 + c)*32 + o];                 // W[0,2]
    else               v = W[(320 + c)*32 + o];                 // W[1,2]
    g_Wcat[idx] = v;
}

// ---------------- encoder: one CTA per window ----------------
__global__ void __launch_bounds__(512) k_enc(
    const float* __restrict__ inputs,
    const float* __restrict__ c1w, const float* __restrict__ c1b,
    const float* __restrict__ g1,  const float* __restrict__ b1,
    const float* __restrict__ c2w, const float* __restrict__ c2b,
    const float* __restrict__ g2,  const float* __restrict__ b2) {

    __shared__ float sw1[256];
    __shared__ float sw2[4096];
    __shared__ float sS[32][16], sQ[32][16];
    __shared__ float sa[32], ssh[32];

    int w = blockIdx.x, t = threadIdx.x;
    int lane = t & 31, wid = t >> 5;

    for (int i = t; i < 256;  i += 512) sw1[i] = c1w[i];
    for (int i = t; i < 4096; i += 512) sw2[i] = c2w[i];
    __syncthreads();

    float xin[64];
    const float* ip = inputs + (size_t)t * 4096 + (size_t)w * 64;
#pragma unroll
    for (int j = 0; j < 64; j++) xin[j] = ip[j];

    for (int c = 0; c < 32; c++) {
        float wk[8];
#pragma unroll
        for (int k = 0; k < 8; k++) wk[k] = sw1[c*8 + k];
        float bb = c1b[c];
        float sc = 0.f, sq = 0.f;
#pragma unroll
        for (int l = 0; l < 15; l++) {
            float a = bb;
#pragma unroll
            for (int k = 0; k < 8; k++) a += xin[l*4 + k] * wk[k];
            a = fmaxf(a, 0.f);
            sc += a; sq += a * a;
        }
        for (int off = 16; off; off >>= 1) {
            sc += __shfl_down_sync(0xffffffffu, sc, off);
            sq += __shfl_down_sync(0xffffffffu, sq, off);
        }
        if (lane == 0) { sS[c][wid] = sc; sQ[c][wid] = sq; }
    }
    __syncthreads();
    if (t < 32) {
        float sc = 0.f, sq = 0.f;
        for (int i = 0; i < 16; i++) { sc += sS[t][i]; sq += sQ[t][i]; }
        float m = sc * (1.f / 7680.f);
        float v = sq * (1.f / 7680.f) - m * m;
        float a = g1[t] * rsqrtf(v + 1e-5f);
        sa[t] = a; ssh[t] = b1[t] - a * m;
    }
    __syncthreads();

    float acc2[32];
#pragma unroll
    for (int i = 0; i < 32; i++) acc2[i] = 0.f;
    for (int c1 = 0; c1 < 32; c1++) {
        float wk[8];
#pragma unroll
        for (int k = 0; k < 8; k++) wk[k] = sw1[c1*8 + k];
        float bb = c1b[c1], a1 = sa[c1], s1 = ssh[c1];
        float y1[12];
#pragma unroll
        for (int l = 0; l < 12; l++) {
            float a = bb;
#pragma unroll
            for (int k = 0; k < 8; k++) a += xin[l*4 + k] * wk[k];
            y1[l] = a1 * fmaxf(a, 0.f) + s1;
        }
#pragma unroll
        for (int c2 = 0; c2 < 16; c2++) {
            float p0 = 0.f, p1 = 0.f;
#pragma unroll
            for (int k = 0; k < 8; k++) {
                float ww = sw2[(c2*32 + c1)*8 + k];
                p0 += y1[k]     * ww;
                p1 += y1[4 + k] * ww;
            }
            acc2[c2*2]     += p0;
            acc2[c2*2 + 1] += p1;
        }
    }
    for (int c2 = 0; c2 < 16; c2++) {
        float bb = c2b[c2];
        float v0 = fmaxf(acc2[c2*2]   + bb, 0.f);
        float v1 = fmaxf(acc2[c2*2+1] + bb, 0.f);
        acc2[c2*2] = v0; acc2[c2*2+1] = v1;
        float sc = v0 + v1, sq = v0*v0 + v1*v1;
        for (int off = 16; off; off >>= 1) {
            sc += __shfl_down_sync(0xffffffffu, sc, off);
            sq += __shfl_down_sync(0xffffffffu, sq, off);
        }
        if (lane == 0) { sS[c2][wid] = sc; sQ[c2][wid] = sq; }
    }
    __syncthreads();
    if (t < 16) {
        float sc = 0.f, sq = 0.f;
        for (int i = 0; i < 16; i++) { sc += sS[t][i]; sq += sQ[t][i]; }
        float m = sc * (1.f / 1024.f);
        float v = sq * (1.f / 1024.f) - m * m;
        float a = g2[t] * rsqrtf(v + 1e-5f);
        sa[t] = a; ssh[t] = b2[t] - a * m;
    }
    __syncthreads();
    float* xo = g_X + ((size_t)w * NNODE + t) * 32;
#pragma unroll
    for (int c2 = 0; c2 < 16; c2++) {
        xo[c2*2]     = sa[c2] * acc2[c2*2]     + ssh[c2];
        xo[c2*2 + 1] = sa[c2] * acc2[c2*2 + 1] + ssh[c2];
    }
}

// ---------------- x-side propagation precompute ----------------
// mode 0: XF1 = Pf(X), XB1 = Pb(X).
// mode 1: XT2O = 2*Pf(XF1) - X, XT2I = 2*Pb(XB1) - X  (finished Chebyshev-2 terms)
__global__ void k_xprop(int mode) {
    int gw = (blockIdx.x * blockDim.x + threadIdx.x) >> 5;
    int lane = threadIdx.x & 31;
    if (gw >= NWIN * NNODE) return;
    int n = gw & 511, t = gw >> 9;
    size_t base = (size_t)t * (NNODE * 32);
    const float* sf  = mode ? (g_XF1 + base) : (g_X + base);
    const float* sbk = mode ? (g_XB1 + base) : (g_X + base);
    float xv = mode ? g_X[base + n*32 + lane] : 0.f;
    float a0 = 0.f, a1 = 0.f, a2 = 0.f, a3 = 0.f;
    int b0 = g_base_dst[n], b1 = g_base_dst[n + 1];
    int i = b0;
    for (; i + 3 < b1; i += 4) {
        a0 += sf[g_adj_dst_n[i]  *32 + lane] * g_adj_dst_w[i];
        a1 += sf[g_adj_dst_n[i+1]*32 + lane] * g_adj_dst_w[i+1];
        a2 += sf[g_adj_dst_n[i+2]*32 + lane] * g_adj_dst_w[i+2];
        a3 += sf[g_adj_dst_n[i+3]*32 + lane] * g_adj_dst_w[i+3];
    }
    for (; i < b1; i++) a0 += sf[g_adj_dst_n[i]*32 + lane] * g_adj_dst_w[i];
    float rf = (a0 + a1) + (a2 + a3);
    if (mode) g_XT2O[base + n*32 + lane] = 2.f * rf - xv;
    else      g_XF1 [base + n*32 + lane] = rf;
    a0 = a1 = a2 = a3 = 0.f;
    b0 = g_base_src[n]; b1 = g_base_src[n + 1];
    i = b0;
    for (; i + 3 < b1; i += 4) {
        a0 += sbk[g_adj_src_n[i]  *32 + lane] * g_adj_src_w[i];
        a1 += sbk[g_adj_src_n[i+1]*32 + lane] * g_adj_src_w[i+1];
        a2 += sbk[g_adj_src_n[i+2]*32 + lane] * g_adj_src_w[i+2];
        a3 += sbk[g_adj_src_n[i+3]*32 + lane] * g_adj_src_w[i+3];
    }
    for (; i < b1; i++) a0 += sbk[g_adj_src_n[i]*32 + lane] * g_adj_src_w[i];
    float rb = (a0 + a1) + (a2 + a3);
    if (mode) g_XT2I[base + n*32 + lane] = 2.f * rb - xv;
    else      g_XB1 [base + n*32 + lane] = rb;
}

// ---------------- persistent recurrent kernel ----------------
// Two-level arrival tree barrier: 16 CTAs -> group counter (8 groups on
// distinct 128B lines), group-last -> root, root-last resets + bumps gen.
__device__ __forceinline__ void grid_bar(int grp) {
    __syncthreads();
    if (threadIdx.x == 0) {
        __threadfence();                       // release CTA's phase writes
        unsigned gen = g_gen;                  // safe: gen can't advance without us
        unsigned old = atomicAdd(&g_grp[grp*32], 1u);
        if (old == 15u) {
            unsigned ro = atomicAdd(&g_root, 1u);
            if (ro == NGRP - 1u) {
#pragma unroll
                for (int i = 0; i < NGRP; i++) atomicExch(&g_grp[i*32], 0u);
                atomicExch(&g_root, 0u);
                __threadfence();               // resets visible before gen bump
                g_gen = gen + 1u;
            }
        }
        while (g_gen == gen) { }
        __threadfence();                       // acquire + L1 invalidate
    }
    __syncthreads();
}

__device__ __forceinline__ float gatherf(const float* __restrict__ a,
                                         const int* __restrict__ en,
                                         const float* __restrict__ ew,
                                         int deg, int lane) {
    float s0 = 0.f, s1 = 0.f, s2 = 0.f, s3 = 0.f;
    int i = 0;
    for (; i + 3 < deg; i += 4) {
        s0 += a[en[i]   + lane] * ew[i];
        s1 += a[en[i+1] + lane] * ew[i+1];
        s2 += a[en[i+2] + lane] * ew[i+2];
        s3 += a[en[i+3] + lane] * ew[i+3];
    }
    for (; i < deg; i++) s0 += a[en[i] + lane] * ew[i];
    return (s0 + s1) + (s2 + s3);
}

// j-split gate matmul (f32x2 packed): warp w covers j in [w*80, w*80+80) for all 4 nodes.
__device__ __forceinline__ void jsplit2(const float* __restrict__ sW,
                                        const float* __restrict__ scat,
                                        int j0, int lane,
                                        float* az, float* ar) {
    unsigned long long az01 = 0ull, az23 = 0ull, ar01 = 0ull, ar23 = 0ull;
#pragma unroll 4
    for (int jj = 0; jj < 80; jj++) {
        int j = j0 + jj;
        float wzv = sW[j*32 + lane];
        float wrv = sW[10240 + j*32 + lane];
        float4 cv = *(const float4*)&scat[j*4];
        unsigned long long wz2 = pk2(wzv, wzv);
        unsigned long long wr2 = pk2(wrv, wrv);
        unsigned long long c01 = pk2(cv.x, cv.y);
        unsigned long long c23 = pk2(cv.z, cv.w);
        fma2(az01, c01, wz2);
        fma2(az23, c23, wz2);
        fma2(ar01, c01, wr2);
        fma2(ar23, c23, wr2);
    }
    float2 p;
    p = upk2(az01); az[0] = p.x; az[1] = p.y;
    p = upk2(az23); az[2] = p.x; az[3] = p.y;
    p = upk2(ar01); ar[0] = p.x; ar[1] = p.y;
    p = upk2(ar23); ar[2] = p.x; ar[3] = p.y;
}

__device__ __forceinline__ void jsplit1(const float* __restrict__ sW,
                                        const float* __restrict__ scat,
                                        int j0, int lane, float* ah) {
    unsigned long long ah01 = 0ull, ah23 = 0ull;
#pragma unroll 4
    for (int jj = 0; jj < 80; jj++) {
        int j = j0 + jj;
        float whv = sW[20480 + j*32 + lane];
        float4 cv = *(const float4*)&scat[j*4];
        unsigned long long wh2 = pk2(whv, whv);
        unsigned long long c01 = pk2(cv.x, cv.y);
        unsigned long long c23 = pk2(cv.z, cv.w);
        fma2(ah01, c01, wh2);
        fma2(ah23, c23, wh2);
    }
    float2 p;
    p = upk2(ah01); ah[0] = p.x; ah[1] = p.y;
    p = upk2(ah23); ah[2] = p.x; ah[3] = p.y;
}

__global__ void __launch_bounds__(128, 1) k_rnn() {
    extern __shared__ float sm[];
    float* sW    = sm;                       // 30720
    float* sb    = sW + 30720;               // 96
    float* scat  = sb + 96;                  // 1280  [j][node]
    float* spart = scat + 1280;              // 1024  [warp][gate][node][lane]
    int*   einN  = (int*)  (spart + 1024);
    float* einW  = (float*)(einN  + 4*MAXD);
    int*   eoutN = (int*)  (einW  + 4*MAXD);
    float* eoutW = (float*)(eoutN + 4*MAXD);

    const int tid  = threadIdx.x;
    const int lane = tid & 31;
    const int w    = tid >> 5;
    const int n    = blockIdx.x * 4 + w;
    const int grp  = blockIdx.x >> 4;

    for (int i = tid; i < 30720; i += 128) sW[i] = g_Wcat[i];
    for (int i = tid; i < 96;    i += 128) sb[i] = g_bias[i];

    int ib = g_base_dst[n];
    int degin = g_base_dst[n + 1] - ib; if (degin > MAXD) degin = MAXD;
    for (int i = lane; i < degin; i += 32) {
        einN[w*MAXD + i] = g_adj_dst_n[ib + i] * 32;
        einW[w*MAXD + i] = g_adj_dst_w[ib + i];
    }
    int ob = g_base_src[n];
    int degout = g_base_src[n + 1] - ob; if (degout > MAXD) degout = MAXD;
    for (int i = lane; i < degout; i += 32) {
        eoutN[w*MAXD + i] = g_adj_src_n[ob + i] * 32;
        eoutW[w*MAXD + i] = g_adj_src_w[ob + i];
    }
    __syncthreads();

    const int*   eiN = einN  + w*MAXD;
    const float* eiW = einW  + w*MAXD;
    const int*   eoN = eoutN + w*MAXD;
    const float* eoW = eoutW + w*MAXD;
    const int no = n*32 + lane;
    const int j0 = w * 80;

    // prefetch step-0 x-streams (fly during other CTAs' startup)
    float x    = g_X[no];
    float xf1  = g_XF1[no],  xb1  = g_XB1[no];
    float xt2o = g_XT2O[no], xt2i = g_XT2I[no];

    // register-carried recurrent state: g_H[no] is single-writer (this lane),
    // H0 = 0 per the reference, so never reload it from memory.
    float h = 0.f;

    for (int t = 0; t < NWIN; t++) {
        // ---- P1: t1 of H ----
        float hf1 = gatherf(g_H, eiN, eiW, degin,  lane);
        float hb1 = gatherf(g_H, eoN, eoW, degout, lane);
        g_HF1[no] = hf1; g_HB1[no] = hb1;
        grid_bar(grp);

        // ---- P2: t2 of H, gates Z/R, v = R*H ----
        float hf2 = gatherf(g_HF1, eiN, eiW, degin,  lane);
        float hb2 = gatherf(g_HB1, eoN, eoW, degout, lane);
        scat[(lane      )*4 + w] = x;
        scat[(32  + lane)*4 + w] = h;
        scat[(64  + lane)*4 + w] = xf1;
        scat[(96  + lane)*4 + w] = hf1;
        scat[(128 + lane)*4 + w] = xb1;
        scat[(160 + lane)*4 + w] = hb1;
        scat[(192 + lane)*4 + w] = xt2o;
        scat[(224 + lane)*4 + w] = 2.f*hf2 - h;
        scat[(256 + lane)*4 + w] = xt2i;
        scat[(288 + lane)*4 + w] = 2.f*hb2 - h;
        __syncthreads();
        {
            float az[4], ar[4];
            jsplit2(sW, scat, j0, lane, az, ar);
#pragma unroll
            for (int nn = 0; nn < 4; nn++) {
                spart[w*256 + 0   + nn*32 + lane] = az[nn];
                spart[w*256 + 128 + nn*32 + lane] = ar[nn];
            }
        }
        __syncthreads();
        {
            float az = sb[lane]      + spart[0*256 + w*32 + lane] + spart[1*256 + w*32 + lane]
                                     + spart[2*256 + w*32 + lane] + spart[3*256 + w*32 + lane];
            float ar = sb[32 + lane] + spart[0*256 + 128 + w*32 + lane] + spart[1*256 + 128 + w*32 + lane]
                                     + spart[2*256 + 128 + w*32 + lane] + spart[3*256 + 128 + w*32 + lane];
            float Z = 1.f / (1.f + expf(-az));
            float R = 1.f / (1.f + expf(-ar));
            float v = R * h;
            g_V[no] = v;
            hf2 = Z;      // stash across phases in registers
            hb2 = v;
        }
        grid_bar(grp);
        float Z = hf2, v = hb2;

        // ---- P3: t1 of v ----
        float vf1 = gatherf(g_V, eiN, eiW, degin,  lane);
        float vb1 = gatherf(g_V, eoN, eoW, degout, lane);
        g_VF1[no] = vf1; g_VB1[no] = vb1;
        grid_bar(grp);

        // ---- P4: t2 of v, Ht, update H ----
        float vf2 = gatherf(g_VF1, eiN, eiW, degin,  lane);
        float vb2 = gatherf(g_VB1, eoN, eoW, degout, lane);
        scat[(lane      )*4 + w] = x;
        scat[(32  + lane)*4 + w] = v;
        scat[(64  + lane)*4 + w] = xf1;
        scat[(96  + lane)*4 + w] = vf1;
        scat[(128 + lane)*4 + w] = xb1;
        scat[(160 + lane)*4 + w] = vb1;
        scat[(192 + lane)*4 + w] = xt2o;
        scat[(224 + lane)*4 + w] = 2.f*vf2 - v;
        scat[(256 + lane)*4 + w] = xt2i;
        scat[(288 + lane)*4 + w] = 2.f*vb2 - v;
        __syncthreads();
        {
            float ah[4];
            jsplit1(sW, scat, j0, lane, ah);
#pragma unroll
            for (int nn = 0; nn < 4; nn++)
                spart[w*256 + nn*32 + lane] = ah[nn];
        }
        __syncthreads();
        {
            float ah = sb[64 + lane] + spart[0*256 + w*32 + lane] + spart[1*256 + w*32 + lane]
                                     + spart[2*256 + w*32 + lane] + spart[3*256 + w*32 + lane];
            float Ht = tanhf(ah);
            float hn = fmaxf(Z * h + (1.f - Z) * Ht, 0.f);
            g_H[no] = hn;
            h = hn;                      // carry state in register
        }
        // prefetch next step's x-streams so they fly during the barrier spin
        if (t + 1 < NWIN) {
            size_t xoff = (size_t)(t + 1) * (NNODE*32) + no;
            x    = g_X[xoff];
            xf1  = g_XF1[xoff];  xb1  = g_XB1[xoff];
            xt2o = g_XT2O[xoff]; xt2i = g_XT2I[xoff];
        }
        grid_bar(grp);
    }
}

// ---------------- readout ----------------
__global__ void k_lin1(const float* __restrict__ wmat, const float* __restrict__ b) {
    int r = blockIdx.x * 8 + (threadIdx.x >> 5);
    int lane = threadIdx.x & 31;
    if (r >= 8192) return;
    const float4* wr4 = (const float4*)(wmat + (size_t)r * 16384);
    const float4* h4  = (const float4*)g_H;
    float a = 0.f;
#pragma unroll 4
    for (int i = lane; i < 4096; i += 32) {
        float4 xx = __ldcs(&wr4[i]);     // streaming: single-use weight rows
        float4 yy = h4[i];
        a += xx.x*yy.x + xx.y*yy.y + xx.z*yy.z + xx.w*yy.w;
    }
    for (int off = 16; off; off >>= 1) a += __shfl_down_sync(0xffffffffu, a, off);
    if (lane == 0) g_lin1out[r] = a + b[r];
}

__global__ void k_cls_reg(const float* __restrict__ c1w, const float* __restrict__ c1b,
                          const float* __restrict__ rw,  const float* __restrict__ rb,
                          float* __restrict__ out) {
    int r = blockIdx.x * 8 + (threadIdx.x >> 5);
    int lane = threadIdx.x & 31;
    if (r >= 3532) return;
    const float4* wr4 = (r < 2048)
        ? (const float4*)(c1w + (size_t)r * 8192)
        : (const float4*)(rw + (size_t)(r - 2048) * 8192);
    const float4* h4 = (const float4*)g_lin1out;
    float a = 0.f;
#pragma unroll 4
    for (int i = lane; i < 2048; i += 32) {
        float4 xx = __ldcs(&wr4[i]);     // streaming: single-use weight rows
        float4 yy = h4[i];
        a += xx.x*yy.x + xx.y*yy.y + xx.z*yy.z + xx.w*yy.w;
    }
    for (int off = 16; off; off >>= 1) a += __shfl_down_sync(0xffffffffu, a, off);
    if (lane == 0) {
        if (r < 2048) g_c1out[r] = a + c1b[r];
        else          out[r - 2048] = a + rb[r - 2048];
    }
}

__global__ void k_angle(const float* __restrict__ w2, const float* __restrict__ b2,
                        float* __restrict__ out) {
    int wi = threadIdx.x >> 5, lane = threadIdx.x & 31;
    if (wi >= 8) return;
    const float4* wr4 = (const float4*)(w2 + (size_t)wi * 2048);
    const float4* h4  = (const float4*)g_c1out;
    float a = 0.f;
    for (int i = lane; i < 512; i += 32) {
        float4 xx = wr4[i], yy = h4[i];
        a += xx.x*yy.x + xx.y*yy.y + xx.z*yy.z + xx.w*yy.w;
    }
    for (int off = 16; off; off >>= 1) a += __shfl_down_sync(0xffffffffu, a, off);
    if (lane == 0) out[1484 + wi] = a + b2[wi];
}

// ---------------- launch ----------------
extern "C" void kernel_launch(void* const* d_in, const int* in_sizes, int n_in,
                              void* d_out, int out_size) {
    const float* inputs = (const float*)d_in[0];
    const int*   ei     = (const int*)  d_in[1];
    const float* c1w  = (const float*)d_in[2];
    const float* c1b  = (const float*)d_in[3];
    const float* bn1g = (const float*)d_in[4];
    const float* bn1b = (const float*)d_in[5];
    const float* c2w  = (const float*)d_in[6];
    const float* c2b  = (const float*)d_in[7];
    const float* bn2g = (const float*)d_in[8];
    const float* bn2b = (const float*)d_in[9];
    const float* wz   = (const float*)d_in[10];
    const float* bz   = (const float*)d_in[11];
    const float* wr   = (const float*)d_in[12];
    const float* br   = (const float*)d_in[13];
    const float* wh   = (const float*)d_in[14];
    const float* bh   = (const float*)d_in[15];
    const float* l1w  = (const float*)d_in[16];
    const float* l1b  = (const float*)d_in[17];
    const float* rw   = (const float*)d_in[18];
    const float* rb   = (const float*)d_in[19];
    const float* cw1  = (const float*)d_in[20];
    const float* cb1  = (const float*)d_in[21];
    const float* cw2  = (const float*)d_in[22];
    const float* cb2  = (const float*)d_in[23];
    float* out = (float*)d_out;

    int rnn_smem = (30720 + 96 + 1280 + 1024) * 4 + 4 * MAXD * 4 * 4;   // 146816 B
    cudaFuncSetAttribute(k_rnn, cudaFuncAttributeMaxDynamicSharedMemorySize, rnn_smem);

    k0<<<64, 256>>>();
    k_deg<<<(NE + 255) / 256, 256>>>(ei);
    k_scan<<<1, 512>>>();
    k_csr<<<128, 256>>>(ei);
    k_wcat<<<(3 * 320 * 32 + 255) / 256, 256>>>(wz, wr, wh, bz, br, bh);
    k_enc<<<64, 512>>>(inputs, c1w, c1b, bn1g, bn1b, c2w, c2b, bn2g, bn2b);
    k_xprop<<<4096, 256>>>(0);
    k_xprop<<<4096, 256>>>(1);
    k_rnn<<<NCTA, 128, rnn_smem>>>();
    k_lin1<<<1024, 256>>>(l1w, l1b);
    k_cls_reg<<<(3532 + 7) / 8, 256>>>(cw1, cb1, rw, rb, out);
    k_angle<<<1, 256>>>(cw2, cb2, out);
}

// round 12
// speedup vs baseline: 1.0648x; 1.0648x over previous
#include <cuda_runtime.h>
#include <math.h>

#define NNODE 512
#define NWIN  64
#define NE    26000
#define NCTA  128
#define MAXD  224
#define NGRP  8          // barrier tree: 8 groups x 16 CTAs

// ---------------- device scratch ----------------
__device__ float g_X  [NWIN*NNODE*32];
__device__ float g_XF1[NWIN*NNODE*32];
__device__ float g_XB1[NWIN*NNODE*32];
__device__ float g_XT2O[NWIN*NNODE*32];   // 2*Pf(XF1) - X
__device__ float g_XT2I[NWIN*NNODE*32];   // 2*Pb(XB1) - X
__device__ float g_H  [NNODE*32];
__device__ float g_V  [NNODE*32];
__device__ float g_HF1[NNODE*32];
__device__ float g_HB1[NNODE*32];
__device__ float g_VF1[NNODE*32];
__device__ float g_VB1[NNODE*32];
__device__ float g_Wcat[3*320*32];
__device__ float g_bias[96];
__device__ int   g_deg_out[NNODE], g_deg_in[NNODE];
__device__ int   g_cnt_dst[NNODE], g_cnt_src[NNODE];
__device__ float g_dinv_out[NNODE], g_dinv_in[NNODE];
__device__ int   g_base_dst[NNODE+1], g_base_src[NNODE+1];
__device__ int   g_adj_dst_n[NE];
__device__ float g_adj_dst_w[NE];
__device__ int   g_adj_src_n[NE];
__device__ float g_adj_src_w[NE];
__device__ unsigned g_grp[NGRP*32];          // group counters, 128B apart
__device__ unsigned g_root;
__device__ unsigned g_gen;
__device__ float g_lin1out[8192];
__device__ float g_c1out[2048];

// ---------------- f32x2 packed math helpers ----------------
__device__ __forceinline__ unsigned long long pk2(float lo, float hi) {
    unsigned long long r;
    asm("mov.b64 %0, {%1, %2};" : "=l"(r) : "f"(lo), "f"(hi));
    return r;
}
__device__ __forceinline__ void fma2(unsigned long long& d, unsigned long long a, unsigned long long b) {
    asm("fma.rn.f32x2 %0, %1, %2, %0;" : "+l"(d) : "l"(a), "l"(b));
}
__device__ __forceinline__ float2 upk2(unsigned long long v) {
    float2 r;
    asm("mov.b64 {%0, %1}, %2;" : "=f"(r.x), "=f"(r.y) : "l"(v));
    return r;
}

// ---------------- acquire/release barrier primitives (no CCTL.IVALL) ----------------
__device__ __forceinline__ unsigned atom_add_acqrel(unsigned* p, unsigned v) {
    unsigned old;
    asm volatile("atom.acq_rel.gpu.global.add.u32 %0, [%1], %2;"
                 : "=r"(old) : "l"(p), "r"(v) : "memory");
    return old;
}
__device__ __forceinline__ unsigned ld_acq(const unsigned* p) {
    unsigned v;
    asm volatile("ld.acquire.gpu.global.u32 %0, [%1];" : "=r"(v) : "l"(p) : "memory");
    return v;
}
__device__ __forceinline__ void st_rel(unsigned* p, unsigned v) {
    asm volatile("st.release.gpu.global.u32 [%0], %1;" :: "l"(p), "r"(v) : "memory");
}

// ---------------- prep kernels ----------------
__global__ void k0() {
    int i = blockIdx.x * blockDim.x + threadIdx.x;
    if (i < NNODE*32) g_H[i] = 0.f;
    if (i < NNODE) { g_deg_in[i] = 0; g_deg_out[i] = 0; g_cnt_dst[i] = 0; g_cnt_src[i] = 0; }
    if (i < NGRP*32) g_grp[i] = 0u;
    if (i == 0) { g_root = 0u; g_gen = 0u; }
}

__global__ void k_deg(const int* __restrict__ ei) {
    int e = blockIdx.x * blockDim.x + threadIdx.x;
    if (e < NE) {
        atomicAdd(&g_deg_out[ei[e]], 1);
        atomicAdd(&g_deg_in [ei[NE + e]], 1);
    }
}

__global__ void k_scan() {   // 1 block, 512 threads
    __shared__ int s[NNODE];
    int t = threadIdx.x;
    int dgi = g_deg_in[t], dgo = g_deg_out[t];
    g_dinv_in [t] = dgi > 0 ? 1.f / (float)dgi : 0.f;
    g_dinv_out[t] = dgo > 0 ? 1.f / (float)dgo : 0.f;
    s[t] = dgi; __syncthreads();
    for (int off = 1; off < NNODE; off <<= 1) {
        int v = (t >= off) ? s[t - off] : 0;
        __syncthreads(); s[t] += v; __syncthreads();
    }
    g_base_dst[t + 1] = s[t];
    if (t == 0) g_base_dst[0] = 0;
    __syncthreads();
    s[t] = dgo; __syncthreads();
    for (int off = 1; off < NNODE; off <<= 1) {
        int v = (t >= off) ? s[t - off] : 0;
        __syncthreads(); s[t] += v; __syncthreads();
    }
    g_base_src[t + 1] = s[t];
    if (t == 0) g_base_src[0] = 0;
}

// edge-parallel bucket fill: store EDGE IDs (temp) into CSR slots (arbitrary order)
__global__ void k_fill(const int* __restrict__ ei) {
    int e = blockIdx.x * blockDim.x + threadIdx.x;
    if (e >= NE) return;
    int s = ei[e], d = ei[NE + e];
    int p = atomicAdd(&g_cnt_dst[d], 1);
    g_adj_dst_n[g_base_dst[d] + p] = e;
    int q = atomicAdd(&g_cnt_src[s], 1);
    g_adj_src_n[g_base_src[s] + q] = e;
}

// per-warp deterministic sort by edge id, then finalize (node, weight) arrays
__global__ void k_sort(const int* __restrict__ ei) {
    int gw = (blockIdx.x * blockDim.x + threadIdx.x) >> 5;
    int lane = threadIdx.x & 31;
    if (gw >= 2 * NNODE) return;
    bool isdst = gw < NNODE;
    int n = isdst ? gw : gw - NNODE;
    int base = isdst ? g_base_dst[n] : g_base_src[n];
    int deg  = (isdst ? g_base_dst[n + 1] : g_base_src[n + 1]) - base;
    int* bucket = isdst ? g_adj_dst_n : g_adj_src_n;

    int keys[8], ranks[8], cnt = 0;
    for (int i = lane; i < deg; i += 32) { if (cnt < 8) keys[cnt++] = bucket[base + i]; }
    for (int c = 0; c < cnt; c++) {
        int k = keys[c], r = 0;
        for (int j = 0; j < deg; j++) r += (bucket[base + j] < k) ? 1 : 0;
        ranks[c] = r;
    }
    __syncwarp();
    for (int c = 0; c < cnt; c++) {
        int e = keys[c];
        int pos = base + ranks[c];
        if (isdst) {
            int sv = ei[e];
            g_adj_dst_n[pos] = sv;
            g_adj_dst_w[pos] = g_dinv_out[sv];
        } else {
            int dv = ei[NE + e];
            g_adj_src_n[pos] = dv;
            g_adj_src_w[pos] = g_dinv_in[dv];
        }
    }
}

// Wcat layout: [gate][j][o], j = blk*64 + c with blocks {xh, t1o, t1i, t2o, t2i}
__global__ void k_wcat(const float* __restrict__ wz, const float* __restrict__ wr,
                       const float* __restrict__ wh, const float* __restrict__ bz,
                       const float* __restrict__ br, const float* __restrict__ bh) {
    int idx = blockIdx.x * blockDim.x + threadIdx.x;
    if (idx < 96) g_bias[idx] = (idx < 32) ? bz[idx] : (idx < 64) ? br[idx-32] : bh[idx-64];
    if (idx >= 3*320*32) return;
    int g = idx / 10240, rem = idx % 10240;
    int j = rem >> 5, o = rem & 31;
    const float* W = (g == 0) ? wz : (g == 1) ? wr : wh;   // [2][3][64][32]
    int c = j & 63, blk = j >> 6;
    float v;
    if      (blk == 0) v = W[c*32 + o] + W[(192 + c)*32 + o];
    else if (blk == 1) v = W[( 64 + c)*32 + o];
    else if (blk == 2) v = W[(256 + c)*32 + o];
    else if (blk == 3) v = W[(128 + c)*32 + o];
    else               v = W[(320 + c)*32 + o];
    g_Wcat[idx] = v;
}

// ---------------- encoder: one CTA per window ----------------
__global__ void __launch_bounds__(512) k_enc(
    const float* __restrict__ inputs,
    const float* __restrict__ c1w, const float* __restrict__ c1b,
    const float* __restrict__ g1,  const float* __restrict__ b1,
    const float* __restrict__ c2w, const float* __restrict__ c2b,
    const float* __restrict__ g2,  const float* __restrict__ b2) {

    __shared__ float sw1[256];
    __shared__ float sw2[4096];
    __shared__ float sS[32][16], sQ[32][16];
    __shared__ float sa[32], ssh[32];

    int w = blockIdx.x, t = threadIdx.x;
    int lane = t & 31, wid = t >> 5;

    for (int i = t; i < 256;  i += 512) sw1[i] = c1w[i];
    for (int i = t; i < 4096; i += 512) sw2[i] = c2w[i];
    __syncthreads();

    float xin[64];
    const float* ip = inputs + (size_t)t * 4096 + (size_t)w * 64;
#pragma unroll
    for (int j = 0; j < 64; j++) xin[j] = ip[j];

    for (int c = 0; c < 32; c++) {
        float wk[8];
#pragma unroll
        for (int k = 0; k < 8; k++) wk[k] = sw1[c*8 + k];
        float bb = c1b[c];
        float sc = 0.f, sq = 0.f;
#pragma unroll
        for (int l = 0; l < 15; l++) {
            float a = bb;
#pragma unroll
            for (int k = 0; k < 8; k++) a += xin[l*4 + k] * wk[k];
            a = fmaxf(a, 0.f);
            sc += a; sq += a * a;
        }
        for (int off = 16; off; off >>= 1) {
            sc += __shfl_down_sync(0xffffffffu, sc, off);
            sq += __shfl_down_sync(0xffffffffu, sq, off);
        }
        if (lane == 0) { sS[c][wid] = sc; sQ[c][wid] = sq; }
    }
    __syncthreads();
    if (t < 32) {
        float sc = 0.f, sq = 0.f;
        for (int i = 0; i < 16; i++) { sc += sS[t][i]; sq += sQ[t][i]; }
        float m = sc * (1.f / 7680.f);
        float v = sq * (1.f / 7680.f) - m * m;
        float a = g1[t] * rsqrtf(v + 1e-5f);
        sa[t] = a; ssh[t] = b1[t] - a * m;
    }
    __syncthreads();

    float acc2[32];
#pragma unroll
    for (int i = 0; i < 32; i++) acc2[i] = 0.f;
    for (int c1 = 0; c1 < 32; c1++) {
        float wk[8];
#pragma unroll
        for (int k = 0; k < 8; k++) wk[k] = sw1[c1*8 + k];
        float bb = c1b[c1], a1 = sa[c1], s1 = ssh[c1];
        float y1[12];
#pragma unroll
        for (int l = 0; l < 12; l++) {
            float a = bb;
#pragma unroll
            for (int k = 0; k < 8; k++) a += xin[l*4 + k] * wk[k];
            y1[l] = a1 * fmaxf(a, 0.f) + s1;
        }
#pragma unroll
        for (int c2 = 0; c2 < 16; c2++) {
            float p0 = 0.f, p1 = 0.f;
#pragma unroll
            for (int k = 0; k < 8; k++) {
                float ww = sw2[(c2*32 + c1)*8 + k];
                p0 += y1[k]     * ww;
                p1 += y1[4 + k] * ww;
            }
            acc2[c2*2]     += p0;
            acc2[c2*2 + 1] += p1;
        }
    }
    for (int c2 = 0; c2 < 16; c2++) {
        float bb = c2b[c2];
        float v0 = fmaxf(acc2[c2*2]   + bb, 0.f);
        float v1 = fmaxf(acc2[c2*2+1] + bb, 0.f);
        acc2[c2*2] = v0; acc2[c2*2+1] = v1;
        float sc = v0 + v1, sq = v0*v0 + v1*v1;
        for (int off = 16; off; off >>= 1) {
            sc += __shfl_down_sync(0xffffffffu, sc, off);
            sq += __shfl_down_sync(0xffffffffu, sq, off);
        }
        if (lane == 0) { sS[c2][wid] = sc; sQ[c2][wid] = sq; }
    }
    __syncthreads();
    if (t < 16) {
        float sc = 0.f, sq = 0.f;
        for (int i = 0; i < 16; i++) { sc += sS[t][i]; sq += sQ[t][i]; }
        float m = sc * (1.f / 1024.f);
        float v = sq * (1.f / 1024.f) - m * m;
        float a = g2[t] * rsqrtf(v + 1e-5f);
        sa[t] = a; ssh[t] = b2[t] - a * m;
    }
    __syncthreads();
    float* xo = g_X + ((size_t)w * NNODE + t) * 32;
#pragma unroll
    for (int c2 = 0; c2 < 16; c2++) {
        xo[c2*2]     = sa[c2] * acc2[c2*2]     + ssh[c2];
        xo[c2*2 + 1] = sa[c2] * acc2[c2*2 + 1] + ssh[c2];
    }
}

// ---------------- x-side propagation precompute ----------------
__global__ void k_xprop(int mode) {
    int gw = (blockIdx.x * blockDim.x + threadIdx.x) >> 5;
    int lane = threadIdx.x & 31;
    if (gw >= NWIN * NNODE) return;
    int n = gw & 511, t = gw >> 9;
    size_t base = (size_t)t * (NNODE * 32);
    const float* sf  = mode ? (g_XF1 + base) : (g_X + base);
    const float* sbk = mode ? (g_XB1 + base) : (g_X + base);
    float xv = mode ? g_X[base + n*32 + lane] : 0.f;
    float a0 = 0.f, a1 = 0.f, a2 = 0.f, a3 = 0.f;
    int b0 = g_base_dst[n], b1 = g_base_dst[n + 1];
    int i = b0;
    for (; i + 3 < b1; i += 4) {
        a0 += sf[g_adj_dst_n[i]  *32 + lane] * g_adj_dst_w[i];
        a1 += sf[g_adj_dst_n[i+1]*32 + lane] * g_adj_dst_w[i+1];
        a2 += sf[g_adj_dst_n[i+2]*32 + lane] * g_adj_dst_w[i+2];
        a3 += sf[g_adj_dst_n[i+3]*32 + lane] * g_adj_dst_w[i+3];
    }
    for (; i < b1; i++) a0 += sf[g_adj_dst_n[i]*32 + lane] * g_adj_dst_w[i];
    float rf = (a0 + a1) + (a2 + a3);
    if (mode) g_XT2O[base + n*32 + lane] = 2.f * rf - xv;
    else      g_XF1 [base + n*32 + lane] = rf;
    a0 = a1 = a2 = a3 = 0.f;
    b0 = g_base_src[n]; b1 = g_base_src[n + 1];
    i = b0;
    for (; i + 3 < b1; i += 4) {
        a0 += sbk[g_adj_src_n[i]  *32 + lane] * g_adj_src_w[i];
        a1 += sbk[g_adj_src_n[i+1]*32 + lane] * g_adj_src_w[i+1];
        a2 += sbk[g_adj_src_n[i+2]*32 + lane] * g_adj_src_w[i+2];
        a3 += sbk[g_adj_src_n[i+3]*32 + lane] * g_adj_src_w[i+3];
    }
    for (; i < b1; i++) a0 += sbk[g_adj_src_n[i]*32 + lane] * g_adj_src_w[i];
    float rb = (a0 + a1) + (a2 + a3);
    if (mode) g_XT2I[base + n*32 + lane] = 2.f * rb - xv;
    else      g_XB1 [base + n*32 + lane] = rb;
}

// ---------------- persistent recurrent kernel ----------------
// Tree barrier with acquire/release semantics ONLY (no membar.gpu / CCTL.IVALL).
// All cross-CTA data uses __ldcg/__stcg (L2-coherent), so L1 staleness is
// impossible and the acq_rel chain through the counters gives ordering.
__device__ __forceinline__ void grid_bar(int grp) {
    __syncthreads();
    if (threadIdx.x == 0) {
        unsigned gen = ld_acq(&g_gen);
        unsigned old = atom_add_acqrel(&g_grp[grp*32], 1u);   // release: prior __stcg ordered
        if (old == 15u) {
            unsigned ro = atom_add_acqrel(&g_root, 1u);
            if (ro == NGRP - 1u) {
#pragma unroll
                for (int i = 0; i < NGRP; i++) g_grp[i*32] = 0u;  // plain; ordered by st.release below
                g_root = 0u;
                st_rel(&g_gen, gen + 1u);
            }
        }
        while (ld_acq(&g_gen) == gen) { }
    }
    __syncthreads();
}

__device__ __forceinline__ float gatherf(const float* __restrict__ a,
                                         const int* __restrict__ en,
                                         const float* __restrict__ ew,
                                         int deg, int lane) {
    float s0 = 0.f, s1 = 0.f, s2 = 0.f, s3 = 0.f;
    int i = 0;
    for (; i + 3 < deg; i += 4) {
        s0 += __ldcg(a + en[i]   + lane) * ew[i];
        s1 += __ldcg(a + en[i+1] + lane) * ew[i+1];
        s2 += __ldcg(a + en[i+2] + lane) * ew[i+2];
        s3 += __ldcg(a + en[i+3] + lane) * ew[i+3];
    }
    for (; i < deg; i++) s0 += __ldcg(a + en[i] + lane) * ew[i];
    return (s0 + s1) + (s2 + s3);
}

// j-split gate matmul (f32x2 packed): warp w covers j in [w*80, w*80+80) for all 4 nodes.
__device__ __forceinline__ void jsplit2(const float* __restrict__ sW,
                                        const float* __restrict__ scat,
                                        int j0, int lane,
                                        float* az, float* ar) {
    unsigned long long az01 = 0ull, az23 = 0ull, ar01 = 0ull, ar23 = 0ull;
#pragma unroll 4
    for (int jj = 0; jj < 80; jj++) {
        int j = j0 + jj;
        float wzv = sW[j*32 + lane];
        float wrv = sW[10240 + j*32 + lane];
        float4 cv = *(const float4*)&scat[j*4];
        unsigned long long wz2 = pk2(wzv, wzv);
        unsigned long long wr2 = pk2(wrv, wrv);
        unsigned long long c01 = pk2(cv.x, cv.y);
        unsigned long long c23 = pk2(cv.z, cv.w);
        fma2(az01, c01, wz2);
        fma2(az23, c23, wz2);
        fma2(ar01, c01, wr2);
        fma2(ar23, c23, wr2);
    }
    float2 p;
    p = upk2(az01); az[0] = p.x; az[1] = p.y;
    p = upk2(az23); az[2] = p.x; az[3] = p.y;
    p = upk2(ar01); ar[0] = p.x; ar[1] = p.y;
    p = upk2(ar23); ar[2] = p.x; ar[3] = p.y;
}

__device__ __forceinline__ void jsplit1(const float* __restrict__ sW,
                                        const float* __restrict__ scat,
                                        int j0, int lane, float* ah) {
    unsigned long long ah01 = 0ull, ah23 = 0ull;
#pragma unroll 4
    for (int jj = 0; jj < 80; jj++) {
        int j = j0 + jj;
        float whv = sW[20480 + j*32 + lane];
        float4 cv = *(const float4*)&scat[j*4];
        unsigned long long wh2 = pk2(whv, whv);
        unsigned long long c01 = pk2(cv.x, cv.y);
        unsigned long long c23 = pk2(cv.z, cv.w);
        fma2(ah01, c01, wh2);
        fma2(ah23, c23, wh2);
    }
    float2 p;
    p = upk2(ah01); ah[0] = p.x; ah[1] = p.y;
    p = upk2(ah23); ah[2] = p.x; ah[3] = p.y;
}

__global__ void __launch_bounds__(128, 1) k_rnn() {
    extern __shared__ float sm[];
    float* sW    = sm;                       // 30720
    float* sb    = sW + 30720;               // 96
    float* scat  = sb + 96;                  // 1280  [j][node]
    float* spart = scat + 1280;              // 1024  [warp][gate][node][lane]
    int*   einN  = (int*)  (spart + 1024);
    float* einW  = (float*)(einN  + 4*MAXD);
    int*   eoutN = (int*)  (einW  + 4*MAXD);
    float* eoutW = (float*)(eoutN + 4*MAXD);

    const int tid  = threadIdx.x;
    const int lane = tid & 31;
    const int w    = tid >> 5;
    const int n    = blockIdx.x * 4 + w;
    const int grp  = blockIdx.x >> 4;

    for (int i = tid; i < 30720; i += 128) sW[i] = g_Wcat[i];
    for (int i = tid; i < 96;    i += 128) sb[i] = g_bias[i];

    int ib = g_base_dst[n];
    int degin = g_base_dst[n + 1] - ib; if (degin > MAXD) degin = MAXD;
    for (int i = lane; i < degin; i += 32) {
        einN[w*MAXD + i] = g_adj_dst_n[ib + i] * 32;
        einW[w*MAXD + i] = g_adj_dst_w[ib + i];
    }
    int ob = g_base_src[n];
    int degout = g_base_src[n + 1] - ob; if (degout > MAXD) degout = MAXD;
    for (int i = lane; i < degout; i += 32) {
        eoutN[w*MAXD + i] = g_adj_src_n[ob + i] * 32;
        eoutW[w*MAXD + i] = g_adj_src_w[ob + i];
    }
    __syncthreads();

    const int*   eiN = einN  + w*MAXD;
    const float* eiW = einW  + w*MAXD;
    const int*   eoN = eoutN + w*MAXD;
    const float* eoW = eoutW + w*MAXD;
    const int no = n*32 + lane;
    const int j0 = w * 80;

    // prefetch step-0 x-streams
    float x    = g_X[no];
    float xf1  = g_XF1[no],  xb1  = g_XB1[no];
    float xt2o = g_XT2O[no], xt2i = g_XT2I[no];

    // register-carried recurrent state (single-writer lane; H0 = 0)
    float h = 0.f;

    for (int t = 0; t < NWIN; t++) {
        // ---- P1: t1 of H ----
        float hf1 = gatherf(g_H, eiN, eiW, degin,  lane);
        float hb1 = gatherf(g_H, eoN, eoW, degout, lane);
        __stcg(&g_HF1[no], hf1);
        __stcg(&g_HB1[no], hb1);
        grid_bar(grp);

        // ---- P2: t2 of H, gates Z/R, v = R*H ----
        float hf2 = gatherf(g_HF1, eiN, eiW, degin,  lane);
        float hb2 = gatherf(g_HB1, eoN, eoW, degout, lane);
        scat[(lane      )*4 + w] = x;
        scat[(32  + lane)*4 + w] = h;
        scat[(64  + lane)*4 + w] = xf1;
        scat[(96  + lane)*4 + w] = hf1;
        scat[(128 + lane)*4 + w] = xb1;
        scat[(160 + lane)*4 + w] = hb1;
        scat[(192 + lane)*4 + w] = xt2o;
        scat[(224 + lane)*4 + w] = 2.f*hf2 - h;
        scat[(256 + lane)*4 + w] = xt2i;
        scat[(288 + lane)*4 + w] = 2.f*hb2 - h;
        __syncthreads();
        {
            float az[4], ar[4];
            jsplit2(sW, scat, j0, lane, az, ar);
#pragma unroll
            for (int nn = 0; nn < 4; nn++) {
                spart[w*256 + 0   + nn*32 + lane] = az[nn];
                spart[w*256 + 128 + nn*32 + lane] = ar[nn];
            }
        }
        __syncthreads();
        {
            float az = sb[lane]      + spart[0*256 + w*32 + lane] + spart[1*256 + w*32 + lane]
                                     + spart[2*256 + w*32 + lane] + spart[3*256 + w*32 + lane];
            float ar = sb[32 + lane] + spart[0*256 + 128 + w*32 + lane] + spart[1*256 + 128 + w*32 + lane]
                                     + spart[2*256 + 128 + w*32 + lane] + spart[3*256 + 128 + w*32 + lane];
            float Z = 1.f / (1.f + expf(-az));
            float R = 1.f / (1.f + expf(-ar));
            float v = R * h;
            __stcg(&g_V[no], v);
            hf2 = Z;      // stash across phases in registers
            hb2 = v;
        }
        grid_bar(grp);
        float Z = hf2, v = hb2;

        // ---- P3: t1 of v ----
        float vf1 = gatherf(g_V, eiN, eiW, degin,  lane);
        float vb1 = gatherf(g_V, eoN, eoW, degout, lane);
        __stcg(&g_VF1[no], vf1);
        __stcg(&g_VB1[no], vb1);
        grid_bar(grp);

        // ---- P4: t2 of v, Ht, update H ----
        float vf2 = gatherf(g_VF1, eiN, eiW, degin,  lane);
        float vb2 = gatherf(g_VB1, eoN, eoW, degout, lane);
        scat[(lane      )*4 + w] = x;
        scat[(32  + lane)*4 + w] = v;
        scat[(64  + lane)*4 + w] = xf1;
        scat[(96  + lane)*4 + w] = vf1;
        scat[(128 + lane)*4 + w] = xb1;
        scat[(160 + lane)*4 + w] = vb1;
        scat[(192 + lane)*4 + w] = xt2o;
        scat[(224 + lane)*4 + w] = 2.f*vf2 - v;
        scat[(256 + lane)*4 + w] = xt2i;
        scat[(288 + lane)*4 + w] = 2.f*vb2 - v;
        __syncthreads();
        {
            float ah[4];
            jsplit1(sW, scat, j0, lane, ah);
#pragma unroll
            for (int nn = 0; nn < 4; nn++)
                spart[w*256 + nn*32 + lane] = ah[nn];
        }
        __syncthreads();
        {
            float ah = sb[64 + lane] + spart[0*256 + w*32 + lane] + spart[1*256 + w*32 + lane]
                                     + spart[2*256 + w*32 + lane] + spart[3*256 + w*32 + lane];
            float Ht = tanhf(ah);
            float hn = fmaxf(Z * h + (1.f - Z) * Ht, 0.f);
            __stcg(&g_H[no], hn);
            h = hn;                      // carry state in register
        }
        // prefetch next step's x-streams (fly during the barrier)
        if (t + 1 < NWIN) {
            size_t xoff = (size_t)(t + 1) * (NNODE*32) + no;
            x    = g_X[xoff];
            xf1  = g_XF1[xoff];  xb1  = g_XB1[xoff];
            xt2o = g_XT2O[xoff]; xt2i = g_XT2I[xoff];
        }
        grid_bar(grp);
    }
}

// ---------------- readout ----------------
__global__ void k_lin1(const float* __restrict__ wmat, const float* __restrict__ b) {
    int r = blockIdx.x * 8 + (threadIdx.x >> 5);
    int lane = threadIdx.x & 31;
    if (r >= 8192) return;
    const float4* wr4 = (const float4*)(wmat + (size_t)r * 16384);
    const float4* h4  = (const float4*)g_H;
    float a = 0.f;
#pragma unroll 4
    for (int i = lane; i < 4096; i += 32) {
        float4 xx = __ldcs(&wr4[i]);
        float4 yy = h4[i];
        a += xx.x*yy.x + xx.y*yy.y + xx.z*yy.z + xx.w*yy.w;
    }
    for (int off = 16; off; off >>= 1) a += __shfl_down_sync(0xffffffffu, a, off);
    if (lane == 0) g_lin1out[r] = a + b[r];
}

__global__ void k_cls_reg(const float* __restrict__ c1w, const float* __restrict__ c1b,
                          const float* __restrict__ rw,  const float* __restrict__ rb,
                          float* __restrict__ out) {
    int r = blockIdx.x * 8 + (threadIdx.x >> 5);
    int lane = threadIdx.x & 31;
    if (r >= 3532) return;
    const float4* wr4 = (r < 2048)
        ? (const float4*)(c1w + (size_t)r * 8192)
        : (const float4*)(rw + (size_t)(r - 2048) * 8192);
    const float4* h4 = (const float4*)g_lin1out;
    float a = 0.f;
#pragma unroll 4
    for (int i = lane; i < 2048; i += 32) {
        float4 xx = __ldcs(&wr4[i]);
        float4 yy = h4[i];
        a += xx.x*yy.x + xx.y*yy.y + xx.z*yy.z + xx.w*yy.w;
    }
    for (int off = 16; off; off >>= 1) a += __shfl_down_sync(0xffffffffu, a, off);
    if (lane == 0) {
        if (r < 2048) g_c1out[r] = a + c1b[r];
        else          out[r - 2048] = a + rb[r - 2048];
    }
}

__global__ void k_angle(const float* __restrict__ w2, const float* __restrict__ b2,
                        float* __restrict__ out) {
    int wi = threadIdx.x >> 5, lane = threadIdx.x & 31;
    if (wi >= 8) return;
    const float4* wr4 = (const float4*)(w2 + (size_t)wi * 2048);
    const float4* h4  = (const float4*)g_c1out;
    float a = 0.f;
    for (int i = lane; i < 512; i += 32) {
        float4 xx = wr4[i], yy = h4[i];
        a += xx.x*yy.x + xx.y*yy.y + xx.z*yy.z + xx.w*yy.w;
    }
    for (int off = 16; off; off >>= 1) a += __shfl_down_sync(0xffffffffu, a, off);
    if (lane == 0) out[1484 + wi] = a + b2[wi];
}

// ---------------- launch ----------------
extern "C" void kernel_launch(void* const* d_in, const int* in_sizes, int n_in,
                              void* d_out, int out_size) {
    const float* inputs = (const float*)d_in[0];
    const int*   ei     = (const int*)  d_in[1];
    const float* c1w  = (const float*)d_in[2];
    const float* c1b  = (const float*)d_in[3];
    const float* bn1g = (const float*)d_in[4];
    const float* bn1b = (const float*)d_in[5];
    const float* c2w  = (const float*)d_in[6];
    const float* c2b  = (const float*)d_in[7];
    const float* bn2g = (const float*)d_in[8];
    const float* bn2b = (const float*)d_in[9];
    const float* wz   = (const float*)d_in[10];
    const float* bz   = (const float*)d_in[11];
    const float* wr   = (const float*)d_in[12];
    const float* br   = (const float*)d_in[13];
    const float* wh   = (const float*)d_in[14];
    const float* bh   = (const float*)d_in[15];
    const float* l1w  = (const float*)d_in[16];
    const float* l1b  = (const float*)d_in[17];
    const float* rw   = (const float*)d_in[18];
    const float* rb   = (const float*)d_in[19];
    const float* cw1  = (const float*)d_in[20];
    const float* cb1  = (const float*)d_in[21];
    const float* cw2  = (const float*)d_in[22];
    const float* cb2  = (const float*)d_in[23];
    float* out = (float*)d_out;

    int rnn_smem = (30720 + 96 + 1280 + 1024) * 4 + 4 * MAXD * 4 * 4;   // 146816 B
    cudaFuncSetAttribute(k_rnn, cudaFuncAttributeMaxDynamicSharedMemorySize, rnn_smem);

    k0<<<64, 256>>>();
    k_deg<<<(NE + 255) / 256, 256>>>(ei);
    k_scan<<<1, 512>>>();
    k_fill<<<(NE + 255) / 256, 256>>>(ei);
    k_sort<<<128, 256>>>(ei);
    k_wcat<<<(3 * 320 * 32 + 255) / 256, 256>>>(wz, wr, wh, bz, br, bh);
    k_enc<<<64, 512>>>(inputs, c1w, c1b, bn1g, bn1b, c2w, c2b, bn2g, bn2b);
    k_xprop<<<4096, 256>>>(0);
    k_xprop<<<4096, 256>>>(1);
    k_rnn<<<NCTA, 128, rnn_smem>>>();
    k_lin1<<<1024, 256>>>(l1w, l1b);
    k_cls_reg<<<(3532 + 7) / 8, 256>>>(cw1, cb1, rw, rb, out);
    k_angle<<<1, 256>>>(cw2, cb2, out);
}

// round 15
// speedup vs baseline: 1.3736x; 1.2900x over previous
#include <cuda_runtime.h>
#include <math.h>

#define NNODE 512
#define NWIN  64
#define NE    26000
#define NCTA  128
#define MAXD  224
#define NGRP  8          // barrier tree: 8 groups x 16 CTAs

// ---------------- device scratch ----------------
__device__ float g_X  [NWIN*NNODE*32];
__device__ float g_XF1[NWIN*NNODE*32];
__device__ float g_XB1[NWIN*NNODE*32];
__device__ float g_XT2O[NWIN*NNODE*32];   // 2*Pf(XF1) - X
__device__ float g_XT2I[NWIN*NNODE*32];   // 2*Pb(XB1) - X
__device__ float g_H  [NNODE*32];
__device__ float g_V  [NNODE*32];
__device__ float g_HF1[NNODE*32];
__device__ float g_HB1[NNODE*32];
__device__ float g_VF1[NNODE*32];
__device__ float g_VB1[NNODE*32];
__device__ float g_Wcat[3*320*32];
__device__ float g_bias[96];
__device__ int   g_deg_out[NNODE], g_deg_in[NNODE];
__device__ int   g_cnt_dst[NNODE], g_cnt_src[NNODE];
__device__ float g_dinv_out[NNODE], g_dinv_in[NNODE];
__device__ int   g_base_dst[NNODE+1], g_base_src[NNODE+1];
__device__ int   g_adj_dst_n[NE];
__device__ float g_adj_dst_w[NE];
__device__ int   g_adj_src_n[NE];
__device__ float g_adj_src_w[NE];
__device__ unsigned g_grp[NGRP*32];          // group counters, 128B apart
__device__ unsigned g_root;
__device__ unsigned g_gen;
__device__ float g_lin1out[8192];
__device__ float g_c1out[2048];

// ---------------- f32x2 packed math helpers ----------------
__device__ __forceinline__ unsigned long long pk2(float lo, float hi) {
    unsigned long long r;
    asm("mov.b64 %0, {%1, %2};" : "=l"(r) : "f"(lo), "f"(hi));
    return r;
}
__device__ __forceinline__ void fma2(unsigned long long& d, unsigned long long a, unsigned long long b) {
    asm("fma.rn.f32x2 %0, %1, %2, %0;" : "+l"(d) : "l"(a), "l"(b));
}
__device__ __forceinline__ float2 upk2(unsigned long long v) {
    float2 r;
    asm("mov.b64 {%0, %1}, %2;" : "=f"(r.x), "=f"(r.y) : "l"(v));
    return r;
}

// ---------------- acquire/release barrier primitives ----------------
__device__ __forceinline__ unsigned atom_add_acqrel(unsigned* p, unsigned v) {
    unsigned old;
    asm volatile("atom.acq_rel.gpu.global.add.u32 %0, [%1], %2;"
                 : "=r"(old) : "l"(p), "r"(v) : "memory");
    return old;
}
__device__ __forceinline__ unsigned ld_acq(const unsigned* p) {
    unsigned v;
    asm volatile("ld.acquire.gpu.global.u32 %0, [%1];" : "=r"(v) : "l"(p) : "memory");
    return v;
}
__device__ __forceinline__ void st_rel(unsigned* p, unsigned v) {
    asm volatile("st.release.gpu.global.u32 [%0], %1;" :: "l"(p), "r"(v) : "memory");
}

// ---------------- prep kernels ----------------
__global__ void k0() {
    int i = blockIdx.x * blockDim.x + threadIdx.x;
    if (i < NNODE*32) g_H[i] = 0.f;
    if (i < NNODE) { g_deg_in[i] = 0; g_deg_out[i] = 0; g_cnt_dst[i] = 0; g_cnt_src[i] = 0; }
    if (i < NGRP*32) g_grp[i] = 0u;
    if (i == 0) { g_root = 0u; g_gen = 0u; }
}

__global__ void k_deg(const int* __restrict__ ei) {
    int e = blockIdx.x * blockDim.x + threadIdx.x;
    if (e < NE) {
        atomicAdd(&g_deg_out[ei[e]], 1);
        atomicAdd(&g_deg_in [ei[NE + e]], 1);
    }
}

__global__ void k_scan() {   // 1 block, 512 threads
    __shared__ int s[NNODE];
    int t = threadIdx.x;
    int dgi = g_deg_in[t], dgo = g_deg_out[t];
    g_dinv_in [t] = dgi > 0 ? 1.f / (float)dgi : 0.f;
    g_dinv_out[t] = dgo > 0 ? 1.f / (float)dgo : 0.f;
    s[t] = dgi; __syncthreads();
    for (int off = 1; off < NNODE; off <<= 1) {
        int v = (t >= off) ? s[t - off] : 0;
        __syncthreads(); s[t] += v; __syncthreads();
    }
    g_base_dst[t + 1] = s[t];
    if (t == 0) g_base_dst[0] = 0;
    __syncthreads();
    s[t] = dgo; __syncthreads();
    for (int off = 1; off < NNODE; off <<= 1) {
        int v = (t >= off) ? s[t - off] : 0;
        __syncthreads(); s[t] += v; __syncthreads();
    }
    g_base_src[t + 1] = s[t];
    if (t == 0) g_base_src[0] = 0;
}

// edge-parallel bucket fill: store EDGE IDs (temp) into CSR slots (arbitrary order)
__global__ void k_fill(const int* __restrict__ ei) {
    int e = blockIdx.x * blockDim.x + threadIdx.x;
    if (e >= NE) return;
    int s = ei[e], d = ei[NE + e];
    int p = atomicAdd(&g_cnt_dst[d], 1);
    g_adj_dst_n[g_base_dst[d] + p] = e;
    int q = atomicAdd(&g_cnt_src[s], 1);
    g_adj_src_n[g_base_src[s] + q] = e;
}

// per-warp deterministic sort by edge id, then finalize (node, weight) arrays
__global__ void k_sort(const int* __restrict__ ei) {
    int gw = (blockIdx.x * blockDim.x + threadIdx.x) >> 5;
    int lane = threadIdx.x & 31;
    if (gw >= 2 * NNODE) return;
    bool isdst = gw < NNODE;
    int n = isdst ? gw : gw - NNODE;
    int base = isdst ? g_base_dst[n] : g_base_src[n];
    int deg  = (isdst ? g_base_dst[n + 1] : g_base_src[n + 1]) - base;
    int* bucket = isdst ? g_adj_dst_n : g_adj_src_n;

    int keys[8], ranks[8], cnt = 0;
    for (int i = lane; i < deg; i += 32) { if (cnt < 8) keys[cnt++] = bucket[base + i]; }
    for (int c = 0; c < cnt; c++) {
        int k = keys[c], r = 0;
        for (int j = 0; j < deg; j++) r += (bucket[base + j] < k) ? 1 : 0;
        ranks[c] = r;
    }
    __syncwarp();
    for (int c = 0; c < cnt; c++) {
        int e = keys[c];
        int pos = base + ranks[c];
        if (isdst) {
            int sv = ei[e];
            g_adj_dst_n[pos] = sv;
            g_adj_dst_w[pos] = g_dinv_out[sv];
        } else {
            int dv = ei[NE + e];
            g_adj_src_n[pos] = dv;
            g_adj_src_w[pos] = g_dinv_in[dv];
        }
    }
}

// Wcat layout: [gate][j][o], j = blk*64 + c with blocks {xh, t1o, t1i, t2o, t2i}
__global__ void k_wcat(const float* __restrict__ wz, const float* __restrict__ wr,
                       const float* __restrict__ wh, const float* __restrict__ bz,
                       const float* __restrict__ br, const float* __restrict__ bh) {
    int idx = blockIdx.x * blockDim.x + threadIdx.x;
    if (idx < 96) g_bias[idx] = (idx < 32) ? bz[idx] : (idx < 64) ? br[idx-32] : bh[idx-64];
    if (idx >= 3*320*32) return;
    int g = idx / 10240, rem = idx % 10240;
    int j = rem >> 5, o = rem & 31;
    const float* W = (g == 0) ? wz : (g == 1) ? wr : wh;   // [2][3][64][32]
    int c = j & 63, blk = j >> 6;
    float v;
    if      (blk == 0) v = W[c*32 + o] + W[(192 + c)*32 + o];
    else if (blk == 1) v = W[( 64 + c)*32 + o];
    else if (blk == 2) v = W[(256 + c)*32 + o];
    else if (blk == 3) v = W[(128 + c)*32 + o];
    else               v = W[(320 + c)*32 + o];
    g_Wcat[idx] = v;
}

// ---------------- encoder: one CTA per window ----------------
__global__ void __launch_bounds__(512) k_enc(
    const float* __restrict__ inputs,
    const float* __restrict__ c1w, const float* __restrict__ c1b,
    const float* __restrict__ g1,  const float* __restrict__ b1,
    const float* __restrict__ c2w, const float* __restrict__ c2b,
    const float* __restrict__ g2,  const float* __restrict__ b2) {

    __shared__ float sw1[256];
    __shared__ float sw2[4096];
    __shared__ float sS[32][16], sQ[32][16];
    __shared__ float sa[32], ssh[32];

    int w = blockIdx.x, t = threadIdx.x;
    int lane = t & 31, wid = t >> 5;

    for (int i = t; i < 256;  i += 512) sw1[i] = c1w[i];
    for (int i = t; i < 4096; i += 512) sw2[i] = c2w[i];
    __syncthreads();

    float xin[64];
    const float* ip = inputs + (size_t)t * 4096 + (size_t)w * 64;
#pragma unroll
    for (int j = 0; j < 64; j++) xin[j] = ip[j];

    for (int c = 0; c < 32; c++) {
        float wk[8];
#pragma unroll
        for (int k = 0; k < 8; k++) wk[k] = sw1[c*8 + k];
        float bb = c1b[c];
        float sc = 0.f, sq = 0.f;
#pragma unroll
        for (int l = 0; l < 15; l++) {
            float a = bb;
#pragma unroll
            for (int k = 0; k < 8; k++) a += xin[l*4 + k] * wk[k];
            a = fmaxf(a, 0.f);
            sc += a; sq += a * a;
        }
        for (int off = 16; off; off >>= 1) {
            sc += __shfl_down_sync(0xffffffffu, sc, off);
            sq += __shfl_down_sync(0xffffffffu, sq, off);
        }
        if (lane == 0) { sS[c][wid] = sc; sQ[c][wid] = sq; }
    }
    __syncthreads();
    if (t < 32) {
        float sc = 0.f, sq = 0.f;
        for (int i = 0; i < 16; i++) { sc += sS[t][i]; sq += sQ[t][i]; }
        float m = sc * (1.f / 7680.f);
        float v = sq * (1.f / 7680.f) - m * m;
        float a = g1[t] * rsqrtf(v + 1e-5f);
        sa[t] = a; ssh[t] = b1[t] - a * m;
    }
    __syncthreads();

    float acc2[32];
#pragma unroll
    for (int i = 0; i < 32; i++) acc2[i] = 0.f;
    for (int c1 = 0; c1 < 32; c1++) {
        float wk[8];
#pragma unroll
        for (int k = 0; k < 8; k++) wk[k] = sw1[c1*8 + k];
        float bb = c1b[c1], a1 = sa[c1], s1 = ssh[c1];
        float y1[12];
#pragma unroll
        for (int l = 0; l < 12; l++) {
            float a = bb;
#pragma unroll
            for (int k = 0; k < 8; k++) a += xin[l*4 + k] * wk[k];
            y1[l] = a1 * fmaxf(a, 0.f) + s1;
        }
#pragma unroll
        for (int c2 = 0; c2 < 16; c2++) {
            float p0 = 0.f, p1 = 0.f;
#pragma unroll
            for (int k = 0; k < 8; k++) {
                float ww = sw2[(c2*32 + c1)*8 + k];
                p0 += y1[k]     * ww;
                p1 += y1[4 + k] * ww;
            }
            acc2[c2*2]     += p0;
            acc2[c2*2 + 1] += p1;
        }
    }
    for (int c2 = 0; c2 < 16; c2++) {
        float bb = c2b[c2];
        float v0 = fmaxf(acc2[c2*2]   + bb, 0.f);
        float v1 = fmaxf(acc2[c2*2+1] + bb, 0.f);
        acc2[c2*2] = v0; acc2[c2*2+1] = v1;
        float sc = v0 + v1, sq = v0*v0 + v1*v1;
        for (int off = 16; off; off >>= 1) {
            sc += __shfl_down_sync(0xffffffffu, sc, off);
            sq += __shfl_down_sync(0xffffffffu, sq, off);
        }
        if (lane == 0) { sS[c2][wid] = sc; sQ[c2][wid] = sq; }
    }
    __syncthreads();
    if (t < 16) {
        float sc = 0.f, sq = 0.f;
        for (int i = 0; i < 16; i++) { sc += sS[t][i]; sq += sQ[t][i]; }
        float m = sc * (1.f / 1024.f);
        float v = sq * (1.f / 1024.f) - m * m;
        float a = g2[t] * rsqrtf(v + 1e-5f);
        sa[t] = a; ssh[t] = b2[t] - a * m;
    }
    __syncthreads();
    float* xo = g_X + ((size_t)w * NNODE + t) * 32;
#pragma unroll
    for (int c2 = 0; c2 < 16; c2++) {
        xo[c2*2]     = sa[c2] * acc2[c2*2]     + ssh[c2];
        xo[c2*2 + 1] = sa[c2] * acc2[c2*2 + 1] + ssh[c2];
    }
}

// ---------------- x-side propagation precompute ----------------
__global__ void k_xprop(int mode) {
    int gw = (blockIdx.x * blockDim.x + threadIdx.x) >> 5;
    int lane = threadIdx.x & 31;
    if (gw >= NWIN * NNODE) return;
    int n = gw & 511, t = gw >> 9;
    size_t base = (size_t)t * (NNODE * 32);
    const float* sf  = mode ? (g_XF1 + base) : (g_X + base);
    const float* sbk = mode ? (g_XB1 + base) : (g_X + base);
    float xv = mode ? g_X[base + n*32 + lane] : 0.f;
    float a0 = 0.f, a1 = 0.f, a2 = 0.f, a3 = 0.f;
    int b0 = g_base_dst[n], b1 = g_base_dst[n + 1];
    int i = b0;
    for (; i + 3 < b1; i += 4) {
        a0 += sf[g_adj_dst_n[i]  *32 + lane] * g_adj_dst_w[i];
        a1 += sf[g_adj_dst_n[i+1]*32 + lane] * g_adj_dst_w[i+1];
        a2 += sf[g_adj_dst_n[i+2]*32 + lane] * g_adj_dst_w[i+2];
        a3 += sf[g_adj_dst_n[i+3]*32 + lane] * g_adj_dst_w[i+3];
    }
    for (; i < b1; i++) a0 += sf[g_adj_dst_n[i]*32 + lane] * g_adj_dst_w[i];
    float rf = (a0 + a1) + (a2 + a3);
    if (mode) g_XT2O[base + n*32 + lane] = 2.f * rf - xv;
    else      g_XF1 [base + n*32 + lane] = rf;
    a0 = a1 = a2 = a3 = 0.f;
    b0 = g_base_src[n]; b1 = g_base_src[n + 1];
    i = b0;
    for (; i + 3 < b1; i += 4) {
        a0 += sbk[g_adj_src_n[i]  *32 + lane] * g_adj_src_w[i];
        a1 += sbk[g_adj_src_n[i+1]*32 + lane] * g_adj_src_w[i+1];
        a2 += sbk[g_adj_src_n[i+2]*32 + lane] * g_adj_src_w[i+2];
        a3 += sbk[g_adj_src_n[i+3]*32 + lane] * g_adj_src_w[i+3];
    }
    for (; i < b1; i++) a0 += sbk[g_adj_src_n[i]*32 + lane] * g_adj_src_w[i];
    float rb = (a0 + a1) + (a2 + a3);
    if (mode) g_XT2I[base + n*32 + lane] = 2.f * rb - xv;
    else      g_XB1 [base + n*32 + lane] = rb;
}

// ---------------- persistent recurrent kernel ----------------
// Tree barrier, acquire/release only. Cross-CTA data uses __ldcg/__stcg.
__device__ __forceinline__ void grid_bar(int grp) {
    __syncthreads();
    if (threadIdx.x == 0) {
        unsigned gen = ld_acq(&g_gen);
        unsigned old = atom_add_acqrel(&g_grp[grp*32], 1u);
        if (old == 15u) {
            unsigned ro = atom_add_acqrel(&g_root, 1u);
            if (ro == NGRP - 1u) {
#pragma unroll
                for (int i = 0; i < NGRP; i++) g_grp[i*32] = 0u;
                g_root = 0u;
                st_rel(&g_gen, gen + 1u);
            }
        }
        while (ld_acq(&g_gen) == gen) { }
    }
    __syncthreads();
}

// gather of this warp's HALF of the edges (stride-2 starting at `half`)
__device__ __forceinline__ float gather_half(const float* __restrict__ a,
                                             const int* __restrict__ en,
                                             const float* __restrict__ ew,
                                             int deg, int half, int lane) {
    float s0 = 0.f, s1 = 0.f, s2 = 0.f, s3 = 0.f;
    int i = half;
    for (; i + 6 < deg; i += 8) {
        s0 += __ldcg(a + en[i]   + lane) * ew[i];
        s1 += __ldcg(a + en[i+2] + lane) * ew[i+2];
        s2 += __ldcg(a + en[i+4] + lane) * ew[i+4];
        s3 += __ldcg(a + en[i+6] + lane) * ew[i+6];
    }
    for (; i < deg; i += 2) s0 += __ldcg(a + en[i] + lane) * ew[i];
    return (s0 + s1) + (s2 + s3);
}

// j-split gate matmul (f32x2 packed): warp w covers 20 j for all 4 nodes.
__device__ __forceinline__ void jsplit2(const float* __restrict__ sW,
                                        const float* __restrict__ scat,
                                        int j0, int lane,
                                        float* az, float* ar) {
    unsigned long long az01 = 0ull, az23 = 0ull, ar01 = 0ull, ar23 = 0ull;
#pragma unroll
    for (int jj = 0; jj < 20; jj++) {
        int j = j0 + jj;
        float wzv = sW[j*32 + lane];
        float wrv = sW[10240 + j*32 + lane];
        float4 cv = *(const float4*)&scat[j*4];
        unsigned long long wz2 = pk2(wzv, wzv);
        unsigned long long wr2 = pk2(wrv, wrv);
        unsigned long long c01 = pk2(cv.x, cv.y);
        unsigned long long c23 = pk2(cv.z, cv.w);
        fma2(az01, c01, wz2);
        fma2(az23, c23, wz2);
        fma2(ar01, c01, wr2);
        fma2(ar23, c23, wr2);
    }
    float2 p;
    p = upk2(az01); az[0] = p.x; az[1] = p.y;
    p = upk2(az23); az[2] = p.x; az[3] = p.y;
    p = upk2(ar01); ar[0] = p.x; ar[1] = p.y;
    p = upk2(ar23); ar[2] = p.x; ar[3] = p.y;
}

__device__ __forceinline__ void jsplit1(const float* __restrict__ sW,
                                        const float* __restrict__ scat,
                                        int j0, int lane, float* ah) {
    unsigned long long ah01 = 0ull, ah23 = 0ull;
#pragma unroll
    for (int jj = 0; jj < 20; jj++) {
        int j = j0 + jj;
        float whv = sW[20480 + j*32 + lane];
        float4 cv = *(const float4*)&scat[j*4];
        unsigned long long wh2 = pk2(whv, whv);
        unsigned long long c01 = pk2(cv.x, cv.y);
        unsigned long long c23 = pk2(cv.z, cv.w);
        fma2(ah01, c01, wh2);
        fma2(ah23, c23, wh2);
    }
    float2 p;
    p = upk2(ah01); ah[0] = p.x; ah[1] = p.y;
    p = upk2(ah23); ah[2] = p.x; ah[3] = p.y;
}

// 512 threads = 16 warps. warp w: node = w>>2; role r = w&3: dir = r>>1, half = r&1.
// "primary" warp of a node is r==0: owns x-streams + state registers, does combines.
__global__ void __launch_bounds__(512, 1) k_rnn() {
    extern __shared__ float sm[];
    float* sW    = sm;                        // 30720
    float* sb    = sW + 30720;                // 96
    float* scat  = sb + 96;                   // 1280  [j][node]
    float* spart = scat + 1280;               // 4096  [warp][gate][node][lane]
    float* sgat  = spart + 4096;              // 512   [node][dir][half][lane]
    int*   sdeg  = (int*)(sgat + 512);        // 8     [node][dir]
    int*   einN  = (int*)(sdeg + 8);          // 4*MAXD
    float* einW  = (float*)(einN  + 4*MAXD);
    int*   eoutN = (int*)(einW  + 4*MAXD);
    float* eoutW = (float*)(eoutN + 4*MAXD);

    const int tid  = threadIdx.x;
    const int lane = tid & 31;
    const int w    = tid >> 5;        // 0..15
    const int node = w >> 2;          // 0..3
    const int r    = w & 3;
    const int dir  = r >> 1;
    const int half = r & 1;
    const int nglob = blockIdx.x * 4 + node;
    const int grp  = blockIdx.x >> 4;
    const int no   = nglob * 32 + lane;
    const int j0   = w * 20;

    for (int i = tid; i < 30720; i += 512) sW[i] = g_Wcat[i];
    for (int i = tid; i < 96;    i += 512) sb[i] = g_bias[i];
    if (tid < 8) {
        int nn = tid >> 1, dd = tid & 1;
        int ng = blockIdx.x * 4 + nn;
        int dv = (dd == 0) ? (g_base_dst[ng + 1] - g_base_dst[ng])
                           : (g_base_src[ng + 1] - g_base_src[ng]);
        sdeg[tid] = dv > MAXD ? MAXD : dv;
    }
    __syncthreads();

    if (r == 0) {
        int ib = g_base_dst[nglob];
        int d = sdeg[node*2];
        for (int i = lane; i < d; i += 32) {
            einN[node*MAXD + i] = g_adj_dst_n[ib + i] * 32;
            einW[node*MAXD + i] = g_adj_dst_w[ib + i];
        }
    } else if (r == 1) {
        int ob = g_base_src[nglob];
        int d = sdeg[node*2 + 1];
        for (int i = lane; i < d; i += 32) {
            eoutN[node*MAXD + i] = g_adj_src_n[ob + i] * 32;
            eoutW[node*MAXD + i] = g_adj_src_w[ob + i];
        }
    }
    __syncthreads();

    const int*   myN  = (dir == 0) ? (einN + node*MAXD) : (eoutN + node*MAXD);
    const float* myW  = (dir == 0) ? (einW + node*MAXD) : (eoutW + node*MAXD);
    const int    mydeg = sdeg[node*2 + dir];
    float* mygat = sgat + ((node*2 + dir)*2 + half)*32;
    float* ngat  = sgat + node*4*32;   // base of this node's 4 partial rows

    // primary-only registers
    float x=0.f, xf1=0.f, xb1=0.f, xt2o=0.f, xt2i=0.f;
    float h=0.f, hf1=0.f, hb1=0.f, Z=0.f, vv=0.f;
    if (r == 0) {
        x = g_X[no]; xf1 = g_XF1[no]; xb1 = g_XB1[no];
        xt2o = g_XT2O[no]; xt2i = g_XT2I[no];
    }

    for (int t = 0; t < NWIN; t++) {
        // ---- P1: t1 of H (both dirs read g_H) ----
        mygat[lane] = gather_half(g_H, myN, myW, mydeg, half, lane);
        __syncthreads();
        if (r == 0) {
            hf1 = ngat[lane] + ngat[32 + lane];
            hb1 = ngat[64 + lane] + ngat[96 + lane];
            __stcg(&g_HF1[no], hf1);
            __stcg(&g_HB1[no], hb1);
        }
        grid_bar(grp);

        // ---- P2: t2 of H, gates Z/R, v = R*H ----
        mygat[lane] = gather_half((dir == 0) ? g_HF1 : g_HB1, myN, myW, mydeg, half, lane);
        __syncthreads();
        if (r == 0) {
            float hf2 = ngat[lane] + ngat[32 + lane];
            float hb2 = ngat[64 + lane] + ngat[96 + lane];
            scat[(lane      )*4 + node] = x;
            scat[(32  + lane)*4 + node] = h;
            scat[(64  + lane)*4 + node] = xf1;
            scat[(96  + lane)*4 + node] = hf1;
            scat[(128 + lane)*4 + node] = xb1;
            scat[(160 + lane)*4 + node] = hb1;
            scat[(192 + lane)*4 + node] = xt2o;
            scat[(224 + lane)*4 + node] = 2.f*hf2 - h;
            scat[(256 + lane)*4 + node] = xt2i;
            scat[(288 + lane)*4 + node] = 2.f*hb2 - h;
        }
        __syncthreads();
        {
            float az[4], ar[4];
            jsplit2(sW, scat, j0, lane, az, ar);
#pragma unroll
            for (int nn = 0; nn < 4; nn++) {
                spart[w*256 + 0   + nn*32 + lane] = az[nn];
                spart[w*256 + 128 + nn*32 + lane] = ar[nn];
            }
        }
        __syncthreads();
        if (r == 0) {
            float az = sb[lane], ar = sb[32 + lane];
#pragma unroll
            for (int k = 0; k < 16; k++) {
                az += spart[k*256 + node*32 + lane];
                ar += spart[k*256 + 128 + node*32 + lane];
            }
            Z = 1.f / (1.f + expf(-az));
            float R = 1.f / (1.f + expf(-ar));
            vv = R * h;
            __stcg(&g_V[no], vv);
        }
        grid_bar(grp);

        // ---- P3: t1 of v ----
        mygat[lane] = gather_half(g_V, myN, myW, mydeg, half, lane);
        __syncthreads();
        float vf1 = 0.f, vb1 = 0.f;
        if (r == 0) {
            vf1 = ngat[lane] + ngat[32 + lane];
            vb1 = ngat[64 + lane] + ngat[96 + lane];
            __stcg(&g_VF1[no], vf1);
            __stcg(&g_VB1[no], vb1);
        }
        grid_bar(grp);

        // ---- P4: t2 of v, Ht, update H ----
        mygat[lane] = gather_half((dir == 0) ? g_VF1 : g_VB1, myN, myW, mydeg, half, lane);
        __syncthreads();
        if (r == 0) {
            float vf2 = ngat[lane] + ngat[32 + lane];
            float vb2 = ngat[64 + lane] + ngat[96 + lane];
            scat[(lane      )*4 + node] = x;
            scat[(32  + lane)*4 + node] = vv;
            scat[(64  + lane)*4 + node] = xf1;
            scat[(96  + lane)*4 + node] = vf1;
            scat[(128 + lane)*4 + node] = xb1;
            scat[(160 + lane)*4 + node] = vb1;
            scat[(192 + lane)*4 + node] = xt2o;
            scat[(224 + lane)*4 + node] = 2.f*vf2 - vv;
            scat[(256 + lane)*4 + node] = xt2i;
            scat[(288 + lane)*4 + node] = 2.f*vb2 - vv;
        }
        __syncthreads();
        {
            float ah[4];
            jsplit1(sW, scat, j0, lane, ah);
#pragma unroll
            for (int nn = 0; nn < 4; nn++)
                spart[w*256 + nn*32 + lane] = ah[nn];
        }
        __syncthreads();
        if (r == 0) {
            float ah = sb[64 + lane];
#pragma unroll
            for (int k = 0; k < 16; k++) ah += spart[k*256 + node*32 + lane];
            float Ht = tanhf(ah);
            float hn = fmaxf(Z * h + (1.f - Z) * Ht, 0.f);
            __stcg(&g_H[no], hn);
            h = hn;
            if (t + 1 < NWIN) {
                size_t xoff = (size_t)(t + 1) * (NNODE*32) + no;
                x    = g_X[xoff];
                xf1  = g_XF1[xoff];  xb1  = g_XB1[xoff];
                xt2o = g_XT2O[xoff]; xt2i = g_XT2I[xoff];
            }
        }
        grid_bar(grp);
    }
}

// ---------------- readout ----------------
__global__ void k_lin1(const float* __restrict__ wmat, const float* __restrict__ b) {
    int r = blockIdx.x * 8 + (threadIdx.x >> 5);
    int lane = threadIdx.x & 31;
    if (r >= 8192) return;
    const float4* wr4 = (const float4*)(wmat + (size_t)r * 16384);
    const float4* h4  = (const float4*)g_H;
    float a = 0.f;
#pragma unroll 4
    for (int i = lane; i < 4096; i += 32) {
        float4 xx = __ldcs(&wr4[i]);
        float4 yy = h4[i];
        a += xx.x*yy.x + xx.y*yy.y + xx.z*yy.z + xx.w*yy.w;
    }
    for (int off = 16; off; off >>= 1) a += __shfl_down_sync(0xffffffffu, a, off);
    if (lane == 0) g_lin1out[r] = a + b[r];
}

__global__ void k_cls_reg(const float* __restrict__ c1w, const float* __restrict__ c1b,
                          const float* __restrict__ rw,  const float* __restrict__ rb,
                          float* __restrict__ out) {
    int r = blockIdx.x * 8 + (threadIdx.x >> 5);
    int lane = threadIdx.x & 31;
    if (r >= 3532) return;
    const float4* wr4 = (r < 2048)
        ? (const float4*)(c1w + (size_t)r * 8192)
        : (const float4*)(rw + (size_t)(r - 2048) * 8192);
    const float4* h4 = (const float4*)g_lin1out;
    float a = 0.f;
#pragma unroll 4
    for (int i = lane; i < 2048; i += 32) {
        float4 xx = __ldcs(&wr4[i]);
        float4 yy = h4[i];
        a += xx.x*yy.x + xx.y*yy.y + xx.z*yy.z + xx.w*yy.w;
    }
    for (int off = 16; off; off >>= 1) a += __shfl_down_sync(0xffffffffu, a, off);
    if (lane == 0) {
        if (r < 2048) g_c1out[r] = a + c1b[r];
        else          out[r - 2048] = a + rb[r - 2048];
    }
}

__global__ void k_angle(const float* __restrict__ w2, const float* __restrict__ b2,
                        float* __restrict__ out) {
    int wi = threadIdx.x >> 5, lane = threadIdx.x & 31;
    if (wi >= 8) return;
    const float4* wr4 = (const float4*)(w2 + (size_t)wi * 2048);
    const float4* h4  = (const float4*)g_c1out;
    float a = 0.f;
    for (int i = lane; i < 512; i += 32) {
        float4 xx = wr4[i], yy = h4[i];
        a += xx.x*yy.x + xx.y*yy.y + xx.z*yy.z + xx.w*yy.w;
    }
    for (int off = 16; off; off >>= 1) a += __shfl_down_sync(0xffffffffu, a, off);
    if (lane == 0) out[1484 + wi] = a + b2[wi];
}

// ---------------- launch ----------------
extern "C" void kernel_launch(void* const* d_in, const int* in_sizes, int n_in,
                              void* d_out, int out_size) {
    const float* inputs = (const float*)d_in[0];
    const int*   ei     = (const int*)  d_in[1];
    const float* c1w  = (const float*)d_in[2];
    const float* c1b  = (const float*)d_in[3];
    const float* bn1g = (const float*)d_in[4];
    const float* bn1b = (const float*)d_in[5];
    const float* c2w  = (const float*)d_in[6];
    const float* c2b  = (const float*)d_in[7];
    const float* bn2g = (const float*)d_in[8];
    const float* bn2b = (const float*)d_in[9];
    const float* wz   = (const float*)d_in[10];
    const float* bz   = (const float*)d_in[11];
    const float* wr   = (const float*)d_in[12];
    const float* br   = (const float*)d_in[13];
    const float* wh   = (const float*)d_in[14];
    const float* bh   = (const float*)d_in[15];
    const float* l1w  = (const float*)d_in[16];
    const float* l1b  = (const float*)d_in[17];
    const float* rw   = (const float*)d_in[18];
    const float* rb   = (const float*)d_in[19];
    const float* cw1  = (const float*)d_in[20];
    const float* cb1  = (const float*)d_in[21];
    const float* cw2  = (const float*)d_in[22];
    const float* cb2  = (const float*)d_in[23];
    float* out = (float*)d_out;

    // floats: 30720+96+1280+4096+512 = 36704 ; +8 ints ; + edges 4*(4*MAXD)*4B
    int rnn_smem = 36704 * 4 + 8 * 4 + 4 * (4 * MAXD) * 4;   // 161184 B
    cudaFuncSetAttribute(k_rnn, cudaFuncAttributeMaxDynamicSharedMemorySize, rnn_smem);

    k0<<<64, 256>>>();
    k_deg<<<(NE + 255) / 256, 256>>>(ei);
    k_scan<<<1, 512>>>();
    k_fill<<<(NE + 255) / 256, 256>>>(ei);
    k_sort<<<128, 256>>>(ei);
    k_wcat<<<(3 * 320 * 32 + 255) / 256, 256>>>(wz, wr, wh, bz, br, bh);
    k_enc<<<64, 512>>>(inputs, c1w, c1b, bn1g, bn1b, c2w, c2b, bn2g, bn2b);
    k_xprop<<<4096, 256>>>(0);
    k_xprop<<<4096, 256>>>(1);
    k_rnn<<<NCTA, 512, rnn_smem>>>();
    k_lin1<<<1024, 256>>>(l1w, l1b);
    k_cls_reg<<<(3532 + 7) / 8, 256>>>(cw1, cb1, rw, rb, out);
    k_angle<<<1, 256>>>(cw2, cb2, out);
}